// round 2
// baseline (speedup 1.0000x reference)
#include <cuda_runtime.h>
#include <math.h>

#define N_TOK   8192
#define D_DIM   4096
#define E_NUM   8
#define R_RANK  128
#define SCALING 0.25f

#define TM 32                 // tokens per expert tile
#define KB 32                 // K-chunk (over D) for stage 1
#define DB 32                 // D-chunk for stage 2
#define HS_STRIDE (R_RANK + 4)   // 132: float4-aligned, 4-phase LDS.128 (optimal)
#define S1_STRIDE (KB + 1)       // 33: conflict-free scalar LDS

// ---- scratch (device globals; no allocations allowed) ----
__device__ int   g_cnt[E_NUM];
__device__ int   g_tok[E_NUM][N_TOK];
__device__ float g_wt [E_NUM][N_TOK];

// Zero output (poisoned by harness) and per-expert counters every call.
__global__ void init_kernel(float4* __restrict__ out)
{
    if (blockIdx.x == 0 && threadIdx.x < E_NUM) g_cnt[threadIdx.x] = 0;
    const float4 z = make_float4(0.f, 0.f, 0.f, 0.f);
    size_t idx    = (size_t)blockIdx.x * blockDim.x + threadIdx.x;
    size_t n4     = (size_t)N_TOK * D_DIM / 4;
    size_t stride = (size_t)gridDim.x * blockDim.x;
    for (size_t j = idx; j < n4; j += stride) out[j] = z;
}

// Router: 1 block per token. logits = x·Wr^T + br; top-2; renormalized
// weights computed directly from logits (softmax denominator cancels).
__global__ __launch_bounds__(256) void router_kernel(
    const float* __restrict__ x, const float* __restrict__ Wr,
    const float* __restrict__ br)
{
    const int n   = blockIdx.x;
    const int tid = threadIdx.x;
    const float* xr = x + (size_t)n * D_DIM;

    float acc[E_NUM];
#pragma unroll
    for (int e = 0; e < E_NUM; e++) acc[e] = 0.f;

    for (int d = tid * 4; d < D_DIM; d += 256 * 4) {
        float4 xv = *(const float4*)(xr + d);
#pragma unroll
        for (int e = 0; e < E_NUM; e++) {
            float4 wv = *(const float4*)(Wr + (size_t)e * D_DIM + d);
            acc[e] += xv.x * wv.x + xv.y * wv.y + xv.z * wv.z + xv.w * wv.w;
        }
    }
#pragma unroll
    for (int e = 0; e < E_NUM; e++) {
#pragma unroll
        for (int off = 16; off > 0; off >>= 1)
            acc[e] += __shfl_xor_sync(0xffffffffu, acc[e], off);
    }
    __shared__ float sm[E_NUM][8];
    const int warp = tid >> 5, lane = tid & 31;
    if (lane == 0) {
#pragma unroll
        for (int e = 0; e < E_NUM; e++) sm[e][warp] = acc[e];
    }
    __syncthreads();
    if (tid == 0) {
        float lg[E_NUM];
#pragma unroll
        for (int e = 0; e < E_NUM; e++) {
            float s = 0.f;
#pragma unroll
            for (int w = 0; w < 8; w++) s += sm[e][w];
            lg[e] = s + br[e];
        }
        int i0 = 0;
#pragma unroll
        for (int e = 1; e < E_NUM; e++) if (lg[e] > lg[i0]) i0 = e;
        int i1 = (i0 == 0) ? 1 : 0;
#pragma unroll
        for (int e = 0; e < E_NUM; e++)
            if (e != i0 && lg[e] > lg[i1]) i1 = e;

        float e1  = expf(lg[i1] - lg[i0]);
        float inv = SCALING / (1.f + e1);   // fold LoRA scaling into the gate
        int p0 = atomicAdd(&g_cnt[i0], 1);
        g_tok[i0][p0] = n;  g_wt[i0][p0] = inv;
        int p1 = atomicAdd(&g_cnt[i1], 1);
        g_tok[i1][p1] = n;  g_wt[i1][p1] = e1 * inv;
    }
}

// Fused expert kernel: block = (tile of TM gathered tokens) x (expert e).
// Stage 1: h[TM][128] = X_gather @ A_e^T  (tiled SGEMM over D, weight folded)
// Stage 2: out[tok] += h @ B_e^T          (tiled over D, REDG atomics)
__global__ __launch_bounds__(256) void expert_kernel(
    const float* __restrict__ x, const float* __restrict__ A,
    const float* __restrict__ B, float* __restrict__ out)
{
    const int e    = blockIdx.y;
    const int cnt  = g_cnt[e];
    const int base = blockIdx.x * TM;
    if (base >= cnt) return;
    const int tid = threadIdx.x;

    __shared__ int   stok[TM];
    __shared__ float swt[TM];
    __shared__ float hs[TM * HS_STRIDE];                          // 16.9 KB
    __shared__ float scratch[TM * S1_STRIDE + R_RANK * S1_STRIDE]; // 21.1 KB
    float* xs  = scratch;                      // stage 1: [TM][33]
    float* as_ = scratch + TM * S1_STRIDE;     // stage 1: [128][33]
    float* bs  = scratch;                      // stage 2 reuse: [DB][132]

    if (tid < TM) {
        int p = base + tid;
        if (p < cnt) { stok[tid] = g_tok[e][p];    swt[tid] = g_wt[e][p]; }
        else         { stok[tid] = g_tok[e][base]; swt[tid] = 0.f;        }
    }
    __syncthreads();

    // ---------------- stage 1: h = X @ A_e^T ----------------
    const int tm = tid & 15;   // 2 token rows each
    const int tn = tid >> 4;   // 8 r-cols each
    float rh[2][8];
#pragma unroll
    for (int i = 0; i < 2; i++)
#pragma unroll
        for (int j = 0; j < 8; j++) rh[i][j] = 0.f;

    const int xlr = tid >> 3;          // 32 rows, 8 threads/row
    const int xlk = (tid & 7) * 4;
    const int alr = tid >> 1;          // 128 rows, 2 threads/row
    const int alk = (tid & 1) * 16;
    const float* xrow = x + (size_t)stok[xlr] * D_DIM + xlk;
    const float* arow = A + ((size_t)e * R_RANK + alr) * D_DIM + alk;

    for (int k0 = 0; k0 < D_DIM; k0 += KB) {
        float4 xv = *(const float4*)(xrow + k0);
        xs[xlr * S1_STRIDE + xlk + 0] = xv.x;
        xs[xlr * S1_STRIDE + xlk + 1] = xv.y;
        xs[xlr * S1_STRIDE + xlk + 2] = xv.z;
        xs[xlr * S1_STRIDE + xlk + 3] = xv.w;
#pragma unroll
        for (int c = 0; c < 4; c++) {
            float4 av = *(const float4*)(arow + k0 + c * 4);
            as_[alr * S1_STRIDE + alk + c * 4 + 0] = av.x;
            as_[alr * S1_STRIDE + alk + c * 4 + 1] = av.y;
            as_[alr * S1_STRIDE + alk + c * 4 + 2] = av.z;
            as_[alr * S1_STRIDE + alk + c * 4 + 3] = av.w;
        }
        __syncthreads();
#pragma unroll
        for (int kk = 0; kk < KB; kk++) {
            float a0 = xs[(tm * 2 + 0) * S1_STRIDE + kk];
            float a1 = xs[(tm * 2 + 1) * S1_STRIDE + kk];
#pragma unroll
            for (int j = 0; j < 8; j++) {
                float b = as_[(tn * 8 + j) * S1_STRIDE + kk];
                rh[0][j] = fmaf(a0, b, rh[0][j]);
                rh[1][j] = fmaf(a1, b, rh[1][j]);
            }
        }
        __syncthreads();
    }
    // write h with gate weight folded in
#pragma unroll
    for (int i = 0; i < 2; i++) {
        float w = swt[tm * 2 + i];
#pragma unroll
        for (int j = 0; j < 8; j++)
            hs[(tm * 2 + i) * HS_STRIDE + tn * 8 + j] = rh[i][j] * w;
    }
    __syncthreads();

    // ---------------- stage 2: out += h @ B_e^T ----------------
    const int m2  = tid & 31;          // one token row per thread
    const int dg  = tid >> 5;          // 8 d-groups x 4 cols
    const int bdr = tid >> 3;          // B tile: 32 rows, 8 threads/row
    const int brr = (tid & 7) * 16;
    const float* hrow = hs + m2 * HS_STRIDE;
    float* orow = out + (size_t)stok[m2] * D_DIM + dg * 4;

    for (int d0 = 0; d0 < D_DIM; d0 += DB) {
        const float* brow = B + ((size_t)e * D_DIM + d0 + bdr) * R_RANK + brr;
#pragma unroll
        for (int c = 0; c < 4; c++)
            *(float4*)&bs[bdr * HS_STRIDE + brr + c * 4] =
                *(const float4*)(brow + c * 4);
        __syncthreads();

        float ro[4] = {0.f, 0.f, 0.f, 0.f};
#pragma unroll
        for (int r = 0; r < R_RANK; r += 4) {
            float4 hv = *(const float4*)(hrow + r);
#pragma unroll
            for (int j = 0; j < 4; j++) {
                float4 bv = *(const float4*)&bs[(dg * 4 + j) * HS_STRIDE + r];
                ro[j] = fmaf(hv.x, bv.x, ro[j]);
                ro[j] = fmaf(hv.y, bv.y, ro[j]);
                ro[j] = fmaf(hv.z, bv.z, ro[j]);
                ro[j] = fmaf(hv.w, bv.w, ro[j]);
            }
        }
#pragma unroll
        for (int j = 0; j < 4; j++)
            atomicAdd(orow + d0 + j, ro[j]);   // REDG, no return needed
        __syncthreads();
    }
}

extern "C" void kernel_launch(void* const* d_in, const int* in_sizes, int n_in,
                              void* d_out, int out_size)
{
    (void)in_sizes; (void)n_in; (void)out_size;
    const float* x  = (const float*)d_in[0];
    const float* Wr = (const float*)d_in[1];
    const float* br = (const float*)d_in[2];
    const float* A  = (const float*)d_in[3];
    const float* B  = (const float*)d_in[4];
    float* out = (float*)d_out;

    init_kernel<<<512, 256>>>((float4*)out);
    router_kernel<<<N_TOK, 256>>>(x, Wr, br);
    dim3 grid(N_TOK / TM, E_NUM);   // 256 tiles x 8 experts (early-exit past cnt)
    expert_kernel<<<grid, 256>>>(x, A, B, out);
}

// round 4
// speedup vs baseline: 4.0921x; 4.0921x over previous
#include <cuda_runtime.h>
#include <cstdint>
#include <math.h>

#define N_TOK   8192
#define D_DIM   4096
#define E_NUM   8
#define R_RANK  128
#define SCALING 0.25f
#define MT      64

__device__ int   g_cnt[2][E_NUM];
__device__ int   g_tok[2][E_NUM][N_TOK];
__device__ float g_wt [2][E_NUM][N_TOK];

// ---- dynamic smem layout (bytes) ----
#define SZ_H        (64 * 132 * 4)                 // 33792: H tile [64][132] tf32
#define OFF_S1X(b)  (SZ_H + (b) * 9216)            // X tile [64][36w]  x2
#define OFF_S1A(b)  (SZ_H + 18432 + (b) * 18432)   // A tile [128][36w] x2
#define OFF_S2B(b)  (SZ_H + (b) * 67584)           // B chunk [128][132w] x2 (reuses S1)
#define SMEM_BYTES  (SZ_H + 2 * 67584)             // 168960

__device__ __forceinline__ uint32_t smem_u32(const void* p) {
    uint32_t a;
    asm("{ .reg .u64 t; cvta.to.shared.u64 t, %1; cvt.u32.u64 %0, t; }" : "=r"(a) : "l"(p));
    return a;
}
__device__ __forceinline__ uint32_t cvt_tf32(float f) {
    uint32_t r; asm("cvt.rna.tf32.f32 %0, %1;" : "=r"(r) : "f"(f)); return r;
}
#define CP16(sa, gp) asm volatile("cp.async.cg.shared.global [%0], [%1], 16;" :: "r"(sa), "l"(gp))
#define CPCOMMIT()   asm volatile("cp.async.commit_group;" ::: "memory")
#define CPWAIT(n)    asm volatile("cp.async.wait_group %0;" :: "n"(n) : "memory")

__device__ __forceinline__ void mma8(float* c, const uint32_t* a, const uint32_t* b) {
    asm volatile("mma.sync.aligned.m16n8k8.row.col.f32.tf32.tf32.f32 "
        "{%0,%1,%2,%3}, {%4,%5,%6,%7}, {%8,%9}, {%0,%1,%2,%3};"
        : "+f"(c[0]), "+f"(c[1]), "+f"(c[2]), "+f"(c[3])
        : "r"(a[0]), "r"(a[1]), "r"(a[2]), "r"(a[3]), "r"(b[0]), "r"(b[1]));
}

// ---------------- kernels ----------------
__global__ void reset_kernel() {
    if (threadIdx.x < 2 * E_NUM) ((int*)g_cnt)[threadIdx.x] = 0;
}

__global__ __launch_bounds__(256) void router_kernel(
    const float* __restrict__ x, const float* __restrict__ Wr, const float* __restrict__ br)
{
    const int n = blockIdx.x, tid = threadIdx.x;
    const float* xr = x + (size_t)n * D_DIM;
    float acc[E_NUM];
#pragma unroll
    for (int e = 0; e < E_NUM; e++) acc[e] = 0.f;
    for (int d = tid * 4; d < D_DIM; d += 1024) {
        float4 xv = *(const float4*)(xr + d);
#pragma unroll
        for (int e = 0; e < E_NUM; e++) {
            float4 wv = *(const float4*)(Wr + (size_t)e * D_DIM + d);
            acc[e] += xv.x*wv.x + xv.y*wv.y + xv.z*wv.z + xv.w*wv.w;
        }
    }
#pragma unroll
    for (int e = 0; e < E_NUM; e++)
#pragma unroll
        for (int off = 16; off > 0; off >>= 1)
            acc[e] += __shfl_xor_sync(0xffffffffu, acc[e], off);
    __shared__ float sm[E_NUM][8];
    const int warp = tid >> 5, lane = tid & 31;
    if (lane == 0)
#pragma unroll
        for (int e = 0; e < E_NUM; e++) sm[e][warp] = acc[e];
    __syncthreads();
    if (tid == 0) {
        float lg[E_NUM];
#pragma unroll
        for (int e = 0; e < E_NUM; e++) {
            float s = 0.f;
#pragma unroll
            for (int w = 0; w < 8; w++) s += sm[e][w];
            lg[e] = s + br[e];
        }
        int i0 = 0;
#pragma unroll
        for (int e = 1; e < E_NUM; e++) if (lg[e] > lg[i0]) i0 = e;
        int i1 = (i0 == 0) ? 1 : 0;
#pragma unroll
        for (int e = 0; e < E_NUM; e++) if (e != i0 && lg[e] > lg[i1]) i1 = e;
        float e1  = expf(lg[i1] - lg[i0]);
        float inv = SCALING / (1.f + e1);
        int p0 = atomicAdd(&g_cnt[0][i0], 1);
        g_tok[0][i0][p0] = n;  g_wt[0][i0][p0] = inv;
        int p1 = atomicAdd(&g_cnt[1][i1], 1);
        g_tok[1][i1][p1] = n;  g_wt[1][i1][p1] = e1 * inv;
    }
}

__global__ __launch_bounds__(256, 1)
void expert_kernel(const float* __restrict__ x, const float* __restrict__ A,
                   const float* __restrict__ B, float* __restrict__ out, int slot)
{
    const int e    = blockIdx.y;
    const int cnt  = g_cnt[slot][e];
    const int base = blockIdx.x * MT;
    if (base >= cnt) return;

    extern __shared__ char dsm[];
    __shared__ int   stok[MT];
    __shared__ float swt[MT];

    const int tid  = threadIdx.x;
    const int lane = tid & 31, warp = tid >> 5;
    const int wm = warp >> 2, wn = warp & 3;     // warp grid 2m x 4n
    const int lm = lane >> 2, lk = lane & 3;

    if (tid < MT) {
        int p = base + tid;
        if (p < cnt) { stok[tid] = g_tok[slot][e][p];    swt[tid] = g_wt[slot][e][p]; }
        else         { stok[tid] = g_tok[slot][e][base]; swt[tid] = 0.f;              }
    }
    __syncthreads();

    const uint32_t sb = smem_u32(dsm);

    // ---- cp.async plumbing ----
    // Stage1 X: 2 units/thread: rows tid>>3 and +32, col16 = tid&7
    const int xr0 = tid >> 3, xc = tid & 7;
    const float* xg0 = x + (size_t)stok[xr0]      * D_DIM + xc * 4;
    const float* xg1 = x + (size_t)stok[xr0 + 32] * D_DIM + xc * 4;
    const uint32_t xo0 = (uint32_t)xr0 * 144u + (uint32_t)xc * 16u;
    const uint32_t xo1 = (uint32_t)(xr0 + 32) * 144u + (uint32_t)xc * 16u;
    // Stage1 A: 4 units/thread: rows (tid>>3)+32j
    const float* ag0 = A + ((size_t)e * R_RANK + xr0) * D_DIM + xc * 4;
    const uint32_t ao0 = (uint32_t)xr0 * 144u + (uint32_t)xc * 16u;
    // Stage2 B: 16 units/thread: rows warp+8j, col16 = lane
    const float* bg0 = B + (size_t)e * D_DIM * R_RANK + (size_t)warp * R_RANK + lane * 4;
    const uint32_t bo0 = (uint32_t)warp * 528u + (uint32_t)lane * 16u;

    float c[2][4][4];
#pragma unroll
    for (int mt = 0; mt < 2; mt++)
#pragma unroll
        for (int nt = 0; nt < 4; nt++)
#pragma unroll
            for (int q = 0; q < 4; q++) c[mt][nt][q] = 0.f;

    // ================= stage 1: h = X_g @ A_e^T =================
    {   // prologue: k-tile 0 -> buf 0
        CP16(sb + OFF_S1X(0) + xo0, xg0);
        CP16(sb + OFF_S1X(0) + xo1, xg1);
#pragma unroll
        for (int j = 0; j < 4; j++)
            CP16(sb + OFF_S1A(0) + ao0 + j * 4608u, ag0 + (size_t)j * 32 * D_DIM);
        CPCOMMIT();
    }
    for (int kt = 0; kt < 128; kt++) {
        if (kt + 1 < 128) {
            const int b = (kt + 1) & 1, gk = (kt + 1) * 32;
            CP16(sb + OFF_S1X(b) + xo0, xg0 + gk);
            CP16(sb + OFF_S1X(b) + xo1, xg1 + gk);
#pragma unroll
            for (int j = 0; j < 4; j++)
                CP16(sb + OFF_S1A(b) + ao0 + j * 4608u, ag0 + (size_t)j * 32 * D_DIM + gk);
            CPCOMMIT();
            CPWAIT(1);
        } else {
            CPWAIT(0);
        }
        __syncthreads();
        const float* Xs = (const float*)(dsm + OFF_S1X(kt & 1));
        const float* As = (const float*)(dsm + OFF_S1A(kt & 1));
#pragma unroll
        for (int ks = 0; ks < 4; ks++) {
            const int k0 = ks * 8 + lk;
            uint32_t af[2][4], bf[4][2];
#pragma unroll
            for (int mt = 0; mt < 2; mt++) {
                const int r0 = wm * 32 + mt * 16 + lm;
                af[mt][0] = cvt_tf32(Xs[r0 * 36 + k0]);
                af[mt][1] = cvt_tf32(Xs[(r0 + 8) * 36 + k0]);
                af[mt][2] = cvt_tf32(Xs[r0 * 36 + k0 + 4]);
                af[mt][3] = cvt_tf32(Xs[(r0 + 8) * 36 + k0 + 4]);
            }
#pragma unroll
            for (int nt = 0; nt < 4; nt++) {
                const int n0 = wn * 32 + nt * 8 + lm;
                bf[nt][0] = cvt_tf32(As[n0 * 36 + k0]);
                bf[nt][1] = cvt_tf32(As[n0 * 36 + k0 + 4]);
            }
#pragma unroll
            for (int mt = 0; mt < 2; mt++)
#pragma unroll
                for (int nt = 0; nt < 4; nt++) mma8(c[mt][nt], af[mt], bf[nt]);
        }
        __syncthreads();
    }

    // ---- stage2 chunk0 prefetch (S1 buffers now dead) ----
    {
        CPWAIT(0);
#pragma unroll
        for (int j = 0; j < 16; j++)
            CP16(sb + OFF_S2B(0) + bo0 + j * 4224u, bg0 + (size_t)j * 8 * R_RANK);
        CPCOMMIT();
    }

    // ---- H epilogue: gate-weight + tf32 -> smem ----
    uint32_t* Hs = (uint32_t*)dsm;
    int   tk[2][2]; float ww[2][2]; bool vv[2][2];
#pragma unroll
    for (int mt = 0; mt < 2; mt++)
#pragma unroll
        for (int h = 0; h < 2; h++) {
            const int r = wm * 32 + mt * 16 + lm + h * 8;
            tk[mt][h] = stok[r]; ww[mt][h] = swt[r]; vv[mt][h] = (base + r) < cnt;
        }
#pragma unroll
    for (int mt = 0; mt < 2; mt++)
#pragma unroll
        for (int h = 0; h < 2; h++) {
            const int r = wm * 32 + mt * 16 + lm + h * 8;
#pragma unroll
            for (int nt = 0; nt < 4; nt++) {
                const int col = wn * 32 + nt * 8 + lk * 2;
                uint2 v;
                v.x = cvt_tf32(c[mt][nt][h * 2]     * ww[mt][h]);
                v.y = cvt_tf32(c[mt][nt][h * 2 + 1] * ww[mt][h]);
                *(uint2*)&Hs[r * 132 + col] = v;
            }
        }
    __syncthreads();

    // ================= stage 2: out (+)= H @ B_e^T =================
    for (int ch = 0; ch < 32; ch++) {
        if (ch + 1 < 32) {
            const int b = (ch + 1) & 1;
            const float* gp = bg0 + (size_t)(ch + 1) * 128 * R_RANK;
#pragma unroll
            for (int j = 0; j < 16; j++)
                CP16(sb + OFF_S2B(b) + bo0 + j * 4224u, gp + (size_t)j * 8 * R_RANK);
            CPCOMMIT();
            CPWAIT(1);
        } else {
            CPWAIT(0);
        }
        __syncthreads();
#pragma unroll
        for (int mt = 0; mt < 2; mt++)
#pragma unroll
            for (int nt = 0; nt < 4; nt++)
#pragma unroll
                for (int q = 0; q < 4; q++) c[mt][nt][q] = 0.f;

        const float* Bs = (const float*)(dsm + OFF_S2B(ch & 1));
#pragma unroll
        for (int ks = 0; ks < 16; ks++) {
            const int k0 = ks * 8 + lk;
            uint32_t af[2][4], bf[4][2];
#pragma unroll
            for (int mt = 0; mt < 2; mt++) {
                const int r0 = wm * 32 + mt * 16 + lm;
                af[mt][0] = Hs[r0 * 132 + k0];
                af[mt][1] = Hs[(r0 + 8) * 132 + k0];
                af[mt][2] = Hs[r0 * 132 + k0 + 4];
                af[mt][3] = Hs[(r0 + 8) * 132 + k0 + 4];
            }
#pragma unroll
            for (int nt = 0; nt < 4; nt++) {
                const int n0 = wn * 32 + nt * 8 + lm;
                bf[nt][0] = cvt_tf32(Bs[n0 * 132 + k0]);
                bf[nt][1] = cvt_tf32(Bs[n0 * 132 + k0 + 4]);
            }
#pragma unroll
            for (int mt = 0; mt < 2; mt++)
#pragma unroll
                for (int nt = 0; nt < 4; nt++) mma8(c[mt][nt], af[mt], bf[nt]);
        }
        // epilogue: write this 128-col chunk
        const int d0 = ch * 128;
#pragma unroll
        for (int mt = 0; mt < 2; mt++)
#pragma unroll
            for (int h = 0; h < 2; h++) {
                if (!vv[mt][h]) continue;
                float* op = out + (size_t)tk[mt][h] * D_DIM + d0 + wn * 32 + lk * 2;
                if (slot == 0) {
#pragma unroll
                    for (int nt = 0; nt < 4; nt++)
                        *(float2*)(op + nt * 8) =
                            make_float2(c[mt][nt][h * 2], c[mt][nt][h * 2 + 1]);
                } else {
#pragma unroll
                    for (int nt = 0; nt < 4; nt++) {
                        float2 o = *(const float2*)(op + nt * 8);
                        o.x += c[mt][nt][h * 2];
                        o.y += c[mt][nt][h * 2 + 1];
                        *(float2*)(op + nt * 8) = o;
                    }
                }
            }
        __syncthreads();
    }
}

extern "C" void kernel_launch(void* const* d_in, const int* in_sizes, int n_in,
                              void* d_out, int out_size)
{
    (void)in_sizes; (void)n_in; (void)out_size;
    const float* x  = (const float*)d_in[0];
    const float* Wr = (const float*)d_in[1];
    const float* br = (const float*)d_in[2];
    const float* A  = (const float*)d_in[3];
    const float* B  = (const float*)d_in[4];
    float* out = (float*)d_out;

    cudaFuncSetAttribute(expert_kernel, cudaFuncAttributeMaxDynamicSharedMemorySize, SMEM_BYTES);
    reset_kernel<<<1, 32>>>();
    router_kernel<<<N_TOK, 256>>>(x, Wr, br);
    dim3 grid(N_TOK / MT, E_NUM);
    expert_kernel<<<grid, 256, SMEM_BYTES>>>(x, A, B, out, 0);
    expert_kernel<<<grid, 256, SMEM_BYTES>>>(x, A, B, out, 1);
}